// round 6
// baseline (speedup 1.0000x reference)
#include <cuda_runtime.h>
#include <cuda_bf16.h>
#include <math.h>
#include <stdint.h>

#define B_  32
#define T_  256
#define E_  256            // embedding dim  (V,E,H,K = 50000,256,512,32)
#define H_  512            // hidden dim
#define K_  32
#define V_  50000
#define G4  2048           // 4*H
#define M_  (T_*B_)        // 8192 tokens
#define NEG_ -10000.0f

// ---------------- scratch (static device globals; no allocation) -------------
__device__ float g_xw[2][M_*G4];          // per-dir xw[t*32+b][4H]
__device__ float g_h [2][M_*H_];          // per-dir hidden outputs
__device__ float g_curh[2][2][B_*H_];     // [dir][phase][b*H+u]
__device__ float g_curc[2][B_*H_];
__device__ float g_feats[B_*T_*K_];       // [m][k], m=b*T+t
__device__ unsigned char g_bp[T_*B_*K_];  // backpointers

__device__ __forceinline__ float sigm(float x){ return 1.0f/(1.0f+expf(-x)); }

__global__ void fill_out(float* out, int n, float val)   // diagnostic sentinel
{
    int i = blockIdx.x * blockDim.x + threadIdx.x;
    if (i < n) out[i] = val;
}

// ---------------- 1) fused embedding-gather + input GEMM --------------------
// C[m,n] = sum_e emb[word(m), e] * Wih[n, e]  (n<2048: fwd, else bwd) + bias
// M=8192, N=4096, K=E_=256. 128x128x8 tiles, 256 threads, 8x8 microtile.
__global__ void gemm_xw(const void* __restrict__ sentence, int sent64,
                        const float* __restrict__ emb,
                        const float* __restrict__ Wf,
                        const float* __restrict__ Wb,
                        const float* __restrict__ bf,
                        const float* __restrict__ bb)
{
    __shared__ float As[8][128];
    __shared__ float Bs[8][128];

    const int bx = blockIdx.x;      // 0..31  (N tiles)
    const int by = blockIdx.y;      // 0..63  (M tiles)
    const int tid = threadIdx.x;
    const int tx = tid & 15;
    const int ty = tid >> 4;

    const int arow  = tid >> 1;
    const int acol4 = (tid & 1) * 4;
    const int r  = by * 128 + arow;
    const int tt = r >> 5;
    const int bb_ = r & 31;
    long long w64 = sent64 ? ((const long long*)sentence)[bb_ * T_ + tt]
                           : (long long)((const int*)sentence)[bb_ * T_ + tt];
    unsigned int word = (unsigned int)w64;
    if (word >= V_) word = 0;                 // defensive clamp
    const float* aptr = emb + (size_t)word * E_;

    const int brow  = tid >> 1;
    const int bcol4 = (tid & 1) * 4;
    const int n = bx * 128 + brow;
    const float* wptr = (n < G4) ? (Wf + (size_t)n * E_)
                                 : (Wb + (size_t)(n - G4) * E_);

    float acc[8][8];
    #pragma unroll
    for (int i = 0; i < 8; i++)
        #pragma unroll
        for (int j = 0; j < 8; j++) acc[i][j] = 0.0f;

    for (int k0 = 0; k0 < E_; k0 += 8) {
        float4 a4 = *(const float4*)(aptr + k0 + acol4);
        float4 b4 = *(const float4*)(wptr + k0 + bcol4);
        __syncthreads();
        As[acol4+0][arow] = a4.x; As[acol4+1][arow] = a4.y;
        As[acol4+2][arow] = a4.z; As[acol4+3][arow] = a4.w;
        Bs[bcol4+0][brow] = b4.x; Bs[bcol4+1][brow] = b4.y;
        Bs[bcol4+2][brow] = b4.z; Bs[bcol4+3][brow] = b4.w;
        __syncthreads();
        #pragma unroll
        for (int k = 0; k < 8; k++) {
            float av[8], bv[8];
            *(float4*)&av[0] = *(const float4*)&As[k][ty*8];
            *(float4*)&av[4] = *(const float4*)&As[k][ty*8+4];
            *(float4*)&bv[0] = *(const float4*)&Bs[k][tx*8];
            *(float4*)&bv[4] = *(const float4*)&Bs[k][tx*8+4];
            #pragma unroll
            for (int i = 0; i < 8; i++)
                #pragma unroll
                for (int j = 0; j < 8; j++)
                    acc[i][j] += av[i] * bv[j];
        }
    }

    const int d = bx >> 4;                // direction (uniform per block)
    const int jjbase = bx * 128 - d * G4; // col within direction
    const float* bias = d ? bb : bf;
    float* outp = g_xw[d];
    #pragma unroll
    for (int i = 0; i < 8; i++) {
        const int m = by * 128 + ty * 8 + i;
        const size_t rowo = (size_t)m * G4;
        #pragma unroll
        for (int j = 0; j < 8; j++) {
            const int jj = jjbase + tx * 8 + j;
            outp[rowo + jj] = acc[i][j] + bias[jj];
        }
    }
}

// ---------------- 2) initial state ------------------------------------------
__global__ void init_state(const float* __restrict__ h0,
                           const float* __restrict__ c0)
{
    int i = blockIdx.x * blockDim.x + threadIdx.x;   // 0 .. 2*B*H-1
    int d = i / (B_*H_);
    int r = i % (B_*H_);
    g_curh[d][0][r] = h0[i];
    g_curc[d][r]    = c0[i];
}

// ---------------- 3) one LSTM step, both directions fused -------------------
// grid (64,2): y=direction, x=unit group (8 units/block); warp=unit, lane=batch
#define CH 128
__global__ void step_kernel(int t,
                            const float* __restrict__ Whhf,
                            const float* __restrict__ Whhb)
{
    __shared__ float hs[CH][33];

    const int d    = blockIdx.y;
    const int warp = threadIdx.x >> 5;
    const int lane = threadIdx.x & 31;
    const int u    = blockIdx.x * 8 + warp;
    const int ph   = t & 1;

    const float* W = d ? Whhb : Whhf;
    const float* hprev = g_curh[d][ph];
    const int txw = d ? (T_ - 1 - t) : t;

    const float* Wi = W + (size_t)(u        ) * H_;
    const float* Wf = W + (size_t)(H_   + u ) * H_;
    const float* Wg = W + (size_t)(2*H_ + u ) * H_;
    const float* Wo = W + (size_t)(3*H_ + u ) * H_;

    float ai = 0.f, af = 0.f, ag = 0.f, ao = 0.f;

    for (int c0 = 0; c0 < H_; c0 += CH) {
        __syncthreads();
        for (int i = threadIdx.x; i < CH * 32; i += 256) {
            int hh = i & (CH-1);
            int bb = i >> 7;
            hs[hh][bb] = hprev[bb * H_ + c0 + hh];
        }
        __syncthreads();
        #pragma unroll 8
        for (int h = 0; h < CH; h += 4) {
            float4 wi4 = *(const float4*)(Wi + c0 + h);
            float4 wf4 = *(const float4*)(Wf + c0 + h);
            float4 wg4 = *(const float4*)(Wg + c0 + h);
            float4 wo4 = *(const float4*)(Wo + c0 + h);
            float x0 = hs[h+0][lane];
            float x1 = hs[h+1][lane];
            float x2 = hs[h+2][lane];
            float x3 = hs[h+3][lane];
            ai += wi4.x*x0; ai += wi4.y*x1; ai += wi4.z*x2; ai += wi4.w*x3;
            af += wf4.x*x0; af += wf4.y*x1; af += wf4.z*x2; af += wf4.w*x3;
            ag += wg4.x*x0; ag += wg4.y*x1; ag += wg4.z*x2; ag += wg4.w*x3;
            ao += wo4.x*x0; ao += wo4.y*x1; ao += wo4.z*x2; ao += wo4.w*x3;
        }
    }

    const int b = lane;
    const size_t xwoff = (size_t)(txw * 32 + b) * G4;
    const float* xw = g_xw[d];
    float zi = ai + xw[xwoff            + u];
    float zf = af + xw[xwoff +   H_     + u];
    float zg = ag + xw[xwoff + 2*H_     + u];
    float zo = ao + xw[xwoff + 3*H_     + u];

    float c  = g_curc[d][b * H_ + u];
    float cn = sigm(zf) * c + sigm(zi) * tanhf(zg);
    float hn = sigm(zo) * tanhf(cn);

    g_curc[d][b * H_ + u]         = cn;
    g_curh[d][ph ^ 1][b * H_ + u] = hn;
    g_h[d][(size_t)(txw * 32 + b) * H_ + u] = hn;
}

// ---------------- 4) output projection feats[b,t,k] -------------------------
__global__ void feats_kernel(const float* __restrict__ Wout,
                             const float* __restrict__ bout)
{
    __shared__ float Ws[32][65];
    __shared__ float Rs[32][65];

    const int tid = threadIdx.x;
    const int tok = tid >> 5;
    const int k   = tid & 31;

    const int m = blockIdx.x * 32 + tok;   // m = b*T + t
    float acc = 0.0f;

    for (int j0 = 0; j0 < 2*H_; j0 += 64) {
        __syncthreads();
        for (int i = tid; i < 32*64; i += 1024) {
            int kk = i >> 6, jj = i & 63;
            Ws[kk][jj] = Wout[kk * (2*H_) + j0 + jj];
        }
        for (int i = tid; i < 32*64; i += 1024) {
            int tk = i >> 6, jj = i & 63;
            int mm = blockIdx.x * 32 + tk;
            int bb = mm >> 8, tt = mm & 255;
            int j = j0 + jj;
            float v;
            if (j < H_) v = g_h[0][(size_t)(tt*32 + bb) * H_ + j];
            else        v = g_h[1][(size_t)(tt*32 + bb) * H_ + (j - H_)];
            Rs[tk][jj] = v;
        }
        __syncthreads();
        #pragma unroll
        for (int jj = 0; jj < 64; jj++)
            acc += Ws[k][jj] * Rs[tok][jj];
    }
    g_feats[(size_t)m * K_ + k] = acc + bout[k];
}

// ---------------- 5) Viterbi decode + backtrack ------------------------------
__global__ void viterbi_kernel(const float* __restrict__ trans,
                               float* __restrict__ out, int path_base)
{
    __shared__ float tr[32][33];
    const int tid = threadIdx.x;
    tr[tid >> 5][tid & 31] = trans[tid];
    __syncthreads();

    const int b    = tid >> 5;   // batch (warp)
    const int lane = tid & 31;   // next-tag n

    float v = (lane == 30) ? 0.0f : NEG_;   // START = 30

    for (int t = 0; t < T_; t++) {
        float ft = g_feats[(size_t)(b * T_ + t) * K_ + lane];
        float best = -3.4e38f;
        int   bp   = 0;
        float vcur = v;
        #pragma unroll
        for (int p = 0; p < 32; p++) {
            float vp = __shfl_sync(0xffffffffu, vcur, p);
            float s = vp + tr[lane][p];
            if (s > best) { best = s; bp = p; }   // first-index tie-break
        }
        v = best + ft;
        g_bp[(size_t)(t * 32 + b) * 32 + lane] = (unsigned char)bp;
    }

    float term = v + tr[31][lane];           // STOP = 31

    float bv = term; int bi = lane;
    #pragma unroll
    for (int off = 16; off > 0; off >>= 1) {
        float ov = __shfl_down_sync(0xffffffffu, bv, off);
        int   oi = __shfl_down_sync(0xffffffffu, bi, off);
        if (ov > bv || (ov == bv && oi < bi)) { bv = ov; bi = oi; }
    }
    bi = __shfl_sync(0xffffffffu, bi, 0);
    bv = __shfl_sync(0xffffffffu, bv, 0);

    if (lane == 0) {
        if (path_base > 0) out[b] = bv;     // path_score
        int tag = bi;
        for (int t = T_ - 1; t >= 0; t--) {
            out[path_base + b * T_ + t] = (float)tag;
            tag = g_bp[(size_t)(t * 32 + b) * 32 + tag];
        }
    }
}

// ---------------- launch -----------------------------------------------------
extern "C" void kernel_launch(void* const* d_in, const int* in_sizes, int n_in,
                              void* d_out, int out_size)
{
    // E=256 sizes. emb is unique: 12,800,000 elements / 51,200,000 f32-bytes.
    int unit = 0;   // 1 = elements, 4 = bytes
    for (int i = 0; i < n_in; i++) {
        if (in_sizes[i] == 12800000) { unit = 1; break; }
        if (in_sizes[i] == 51200000) { unit = 4; break; }
    }

    // normalized element-count signature:
    //  sentence 8192 (int32) / 16384-normalized if int64+bytes
    //  emb 12,800,000 | W_ih 524,288 x2 | W_hh 1,048,576 x2 | bias 2048 x2
    //  W_out/h0/c0 32,768 x3 | b_out 32 | trans 1024
    int i_sent = -1, i_emb = -1, i_bout = -1, i_tr = -1, sent64 = 0;
    int gih[2], nih = 0, ghh[2], nhh = 0, g2i[2], n2 = 0, g3i[3], n3 = 0;
    if (unit) {
        for (int i = 0; i < n_in; i++) {
            const int s = in_sizes[i] / unit;
            if      (s == 8192)     { if (i_sent < 0) { i_sent = i; sent64 = 0; } }
            else if (s == 16384)    { if (i_sent < 0) { i_sent = i; sent64 = 1; } }
            else if (s == 12800000) { if (i_emb  < 0) i_emb  = i; }
            else if (s == 32)       { if (i_bout < 0) i_bout = i; }
            else if (s == 1024)     { if (i_tr   < 0) i_tr   = i; }
            else if (s == 524288)   { if (nih < 2) gih[nih++] = i; }
            else if (s == 1048576)  { if (nhh < 2) ghh[nhh++] = i; }
            else if (s == 2048)     { if (n2  < 2) g2i[n2++]  = i; }
            else if (s == 32768)    { if (n3  < 3) g3i[n3++]  = i; }
        }
    }
    const int out_elems = (unit == 4) ? out_size / 4 : out_size;

    if (!unit || i_sent < 0 || i_emb < 0 || i_bout < 0 || i_tr < 0 ||
        nih != 2 || nhh != 2 || n2 != 2 || n3 != 3) {
        int n = out_size > 0 ? out_size : 1;          // sentinel (rel_err >> 1)
        fill_out<<<(n + 255) / 256, 256>>>((float*)d_out, n, 1.0e6f);
        return;
    }

    int I_Wihf, I_Whhf, I_Wihb, I_Whhb, I_bf, I_bb, I_Wout, I_h0, I_c0;
    if (i_sent < i_emb) {
        // dict order: sentence, emb, W_ih_f, W_hh_f, b_f, W_ih_b, W_hh_b, b_b,
        //             W_out, b_out, transitions, h0, c0
        I_Wihf = gih[0]; I_Wihb = gih[1];
        I_Whhf = ghh[0]; I_Whhb = ghh[1];
        I_bf   = g2i[0]; I_bb   = g2i[1];
        I_Wout = g3i[0]; I_h0   = g3i[1]; I_c0 = g3i[2];
    } else {
        // name-sorted: W_hh_b, W_hh_f, W_ih_b, W_ih_f, W_out, b_b, b_f, b_out,
        //              c0, emb, h0, sentence, transitions
        I_Whhb = ghh[0]; I_Whhf = ghh[1];
        I_Wihb = gih[0]; I_Wihf = gih[1];
        I_bb   = g2i[0]; I_bf   = g2i[1];
        I_Wout = g3i[0]; I_c0   = g3i[1]; I_h0 = g3i[2];
    }

    const void*  sentence = d_in[i_sent];
    const float* emb      = (const float*)d_in[i_emb];
    const float* W_ih_f   = (const float*)d_in[I_Wihf];
    const float* W_hh_f   = (const float*)d_in[I_Whhf];
    const float* b_f      = (const float*)d_in[I_bf];
    const float* W_ih_b   = (const float*)d_in[I_Wihb];
    const float* W_hh_b   = (const float*)d_in[I_Whhb];
    const float* b_b      = (const float*)d_in[I_bb];
    const float* W_out    = (const float*)d_in[I_Wout];
    const float* b_out    = (const float*)d_in[i_bout];
    const float* trans    = (const float*)d_in[i_tr];
    const float* h0       = (const float*)d_in[I_h0];
    const float* c0       = (const float*)d_in[I_c0];
    float* out = (float*)d_out;

    const int path_base = (out_elems >= B_ + B_*T_) ? B_ : 0;

    gemm_xw<<<dim3(32, 64), 256>>>(sentence, sent64, emb, W_ih_f, W_ih_b, b_f, b_b);
    init_state<<<64, 512>>>(h0, c0);
    for (int t = 0; t < T_; t++)
        step_kernel<<<dim3(64, 2), 256>>>(t, W_hh_f, W_hh_b);
    feats_kernel<<<256, 1024>>>(W_out, b_out);
    viterbi_kernel<<<1, 1024>>>(trans, out, path_base);
}

// round 7
// speedup vs baseline: 2.1451x; 2.1451x over previous
#include <cuda_runtime.h>
#include <math.h>
#include <stdint.h>

#define B_  32
#define T_  256
#define E_  256            // V,E,H,K = 50000,256,512,32
#define H_  512
#define K_  32
#define V_  50000
#define G4  2048           // 4*H
#define M_  (T_*B_)        // 8192 tokens
#define NEG_ -10000.0f
#define NBLK 128           // persistent grid

// ---------------- scratch (static device globals; no allocation) -------------
__device__ float g_xw [2][M_*G4];         // [d][m][n]           m=t*32+b, n=gate*512+u
__device__ float g_xwT[2][M_*G4];         // [d][(t*2048+n)*32+b]  coalesced per-step reads
__device__ float g_hT [2][M_*H_];         // [d][(t*512+u)*32+b]   h archive
__device__ float g_cur[2][2][H_*B_];      // [d][phase][u*32+b]    ping-pong h state
__device__ float g_feats[B_*T_*K_];       // [m][k], m=b*T+t
__device__ unsigned char g_bp[T_*B_*K_];  // viterbi backpointers
__device__ int g_cnt;                     // grid barrier
__device__ int g_gen;

__device__ __forceinline__ float sigm(float x){ return 1.0f/(1.0f+expf(-x)); }

__global__ void fill_out(float* out, int n, float val)   // diagnostic sentinel
{
    int i = blockIdx.x * blockDim.x + threadIdx.x;
    if (i < n) out[i] = val;
}

// ---------------- 1) fused embedding-gather + input GEMM --------------------
// C[m,n] = sum_e emb[word(m),e] * Wih[n,e] + bias.  M=8192,N=4096,K=256.
__global__ void gemm_xw(const void* __restrict__ sentence, int sent64,
                        const float* __restrict__ emb,
                        const float* __restrict__ Wf,
                        const float* __restrict__ Wb,
                        const float* __restrict__ bf,
                        const float* __restrict__ bb)
{
    __shared__ float As[8][128];
    __shared__ float Bs[8][128];

    const int bx = blockIdx.x;      // 0..31  (N tiles)
    const int by = blockIdx.y;      // 0..63  (M tiles)
    const int tid = threadIdx.x;
    const int tx = tid & 15;
    const int ty = tid >> 4;

    const int arow  = tid >> 1;
    const int acol4 = (tid & 1) * 4;
    const int r  = by * 128 + arow;
    const int tt = r >> 5;
    const int bb_ = r & 31;
    long long w64 = sent64 ? ((const long long*)sentence)[bb_ * T_ + tt]
                           : (long long)((const int*)sentence)[bb_ * T_ + tt];
    unsigned int word = (unsigned int)w64;
    if (word >= V_) word = 0;
    const float* aptr = emb + (size_t)word * E_;

    const int brow  = tid >> 1;
    const int bcol4 = (tid & 1) * 4;
    const int n = bx * 128 + brow;
    const float* wptr = (n < G4) ? (Wf + (size_t)n * E_)
                                 : (Wb + (size_t)(n - G4) * E_);

    float acc[8][8];
    #pragma unroll
    for (int i = 0; i < 8; i++)
        #pragma unroll
        for (int j = 0; j < 8; j++) acc[i][j] = 0.0f;

    for (int k0 = 0; k0 < E_; k0 += 8) {
        float4 a4 = *(const float4*)(aptr + k0 + acol4);
        float4 b4 = *(const float4*)(wptr + k0 + bcol4);
        __syncthreads();
        As[acol4+0][arow] = a4.x; As[acol4+1][arow] = a4.y;
        As[acol4+2][arow] = a4.z; As[acol4+3][arow] = a4.w;
        Bs[bcol4+0][brow] = b4.x; Bs[bcol4+1][brow] = b4.y;
        Bs[bcol4+2][brow] = b4.z; Bs[bcol4+3][brow] = b4.w;
        __syncthreads();
        #pragma unroll
        for (int k = 0; k < 8; k++) {
            float av[8], bv[8];
            *(float4*)&av[0] = *(const float4*)&As[k][ty*8];
            *(float4*)&av[4] = *(const float4*)&As[k][ty*8+4];
            *(float4*)&bv[0] = *(const float4*)&Bs[k][tx*8];
            *(float4*)&bv[4] = *(const float4*)&Bs[k][tx*8+4];
            #pragma unroll
            for (int i = 0; i < 8; i++)
                #pragma unroll
                for (int j = 0; j < 8; j++)
                    acc[i][j] += av[i] * bv[j];
        }
    }

    const int d = bx >> 4;
    const int jjbase = bx * 128 - d * G4;
    const float* bias = d ? bb : bf;
    float* outp = g_xw[d];
    #pragma unroll
    for (int i = 0; i < 8; i++) {
        const int m = by * 128 + ty * 8 + i;
        const size_t rowo = (size_t)m * G4;
        #pragma unroll
        for (int j = 0; j < 8; j++) {
            const int jj = jjbase + tx * 8 + j;
            outp[rowo + jj] = acc[i][j] + bias[jj];
        }
    }
}

// ---------------- 1b) transpose xw:  [m][n] -> [(t*2048+n)*32+b] ------------
// grid (64, 256, 2), block 256
__global__ void xw_transpose()
{
    __shared__ float tile[32][33];
    const int n0 = blockIdx.x * 32;
    const int t  = blockIdx.y;
    const int d  = blockIdx.z;
    const int x  = threadIdx.x & 31;
    const int y  = threadIdx.x >> 5;       // 0..7
    const float* in  = g_xw[d];
    float*       out = g_xwT[d];
    #pragma unroll
    for (int rr = 0; rr < 4; rr++) {
        int b = y * 4 + rr;
        tile[b][x] = in[(size_t)(t*32 + b) * G4 + n0 + x];
    }
    __syncthreads();
    #pragma unroll
    for (int rr = 0; rr < 4; rr++) {
        int nl = y * 4 + rr;
        out[((size_t)t * G4 + n0 + nl) * 32 + x] = tile[x][nl];
    }
}

// ---------------- 2) init: h0 -> cur[phase 0], reset barrier ----------------
__global__ void init_state(const float* __restrict__ h0)
{
    int i = blockIdx.x * blockDim.x + threadIdx.x;   // 0 .. 2*B*H-1
    if (i == 0) { g_cnt = 0; g_gen = 0; }
    if (i < 2*B_*H_) {
        int d = i / (B_*H_);
        int r = i % (B_*H_);
        int b = r / H_, u = r % H_;
        g_cur[d][0][u*32 + b] = h0[i];
    }
}

// ---------------- 3) persistent bidirectional LSTM recurrence ---------------
// 128 blocks x 512 threads, 1 block/SM (137KB smem) => co-resident, software
// grid barrier per step. Block = 8 units x 4 gates of one direction.
// warp = (unit warp&7, k-half warp>>3); lane = batch. c lives in registers.
__global__ void __launch_bounds__(512, 1)
lstm_persist(const float* __restrict__ Whhf,
             const float* __restrict__ Whhb,
             const float* __restrict__ c0)
{
    extern __shared__ float sm[];
    float* Wsm = sm;                 // [32][512]  gate-rows of 8 units
    float* hsm = Wsm + 32*512;       // [512][33]  h_prev, k-major, padded
    float* red = hsm + 512*33;       // [8][4][32] k-split partials

    const int tid  = threadIdx.x;
    const int bid  = blockIdx.x;
    const int warp = tid >> 5;
    const int lane = tid & 31;
    const int d    = bid >> 6;            // direction
    const int ub   = (bid & 63) * 8;      // first unit of this block
    const float* W = d ? Whhb : Whhf;

    // load W tile once: row r = g*8+i  <-  W_hh[(g*512 + ub+i)][k]
    for (int i = tid; i < 32*512; i += 512) {
        int rr = i >> 9, k = i & 511;
        int gg = rr >> 3, ii = rr & 7;
        Wsm[rr*512 + k] = W[(size_t)(gg*H_ + ub + ii)*H_ + k];
    }

    const int u = ub + (warp & 7);        // this warp's unit (gate set)
    float c = 0.0f;
    if (warp < 8) c = c0[d*(B_*H_) + lane*H_ + u];   // c0: [2][B][H]

    const float* xwT = g_xwT[d];
    const int iu = warp & 7, ks = warp >> 3;
    const int k0 = ks * 256;

    for (int t = 0; t < T_; t++) {
        const int ph  = t & 1;
        const int txw = d ? (T_ - 1 - t) : t;

        // prefetch this thread's 4 xw gate values (coalesced, streamed)
        float xi=0.f, xf=0.f, xg=0.f, xo=0.f;
        if (warp < 8) {
            const float* p = xwT + (size_t)txw * G4 * 32 + lane;
            xi = __ldcg(p + (0*H_ + u)*32);
            xf = __ldcg(p + (1*H_ + u)*32);
            xg = __ldcg(p + (2*H_ + u)*32);
            xo = __ldcg(p + (3*H_ + u)*32);
        }

        // stage h_prev (all 512 units) from L2 (bypass L1: cross-step state)
        {
            const float* cp = g_cur[d][ph];
            for (int i = tid; i < H_*B_; i += 512) {
                int uu = i >> 5, b = i & 31;
                hsm[uu*33 + b] = __ldcg(cp + i);
            }
        }
        __syncthreads();

        // 4-gate dot products over this warp's k-half
        float a0=0.f, a1=0.f, a2=0.f, a3=0.f;
        #pragma unroll 4
        for (int q = 0; q < 64; q++) {
            int k = k0 + q*4;
            float h0v = hsm[(k+0)*33 + lane];
            float h1v = hsm[(k+1)*33 + lane];
            float h2v = hsm[(k+2)*33 + lane];
            float h3v = hsm[(k+3)*33 + lane];
            float4 w0 = *(const float4*)&Wsm[(0*8+iu)*512 + k];
            float4 w1 = *(const float4*)&Wsm[(1*8+iu)*512 + k];
            float4 w2 = *(const float4*)&Wsm[(2*8+iu)*512 + k];
            float4 w3 = *(const float4*)&Wsm[(3*8+iu)*512 + k];
            a0 += w0.x*h0v; a0 += w0.y*h1v; a0 += w0.z*h2v; a0 += w0.w*h3v;
            a1 += w1.x*h0v; a1 += w1.y*h1v; a1 += w1.z*h2v; a1 += w1.w*h3v;
            a2 += w2.x*h0v; a2 += w2.y*h1v; a2 += w2.z*h2v; a2 += w2.w*h3v;
            a3 += w3.x*h0v; a3 += w3.y*h1v; a3 += w3.z*h2v; a3 += w3.w*h3v;
        }

        // k-split reduce: upper half warps deposit partials
        if (warp >= 8) {
            red[((warp-8)*4 + 0)*32 + lane] = a0;
            red[((warp-8)*4 + 1)*32 + lane] = a1;
            red[((warp-8)*4 + 2)*32 + lane] = a2;
            red[((warp-8)*4 + 3)*32 + lane] = a3;
        }
        __syncthreads();

        if (warp < 8) {
            a0 += red[(warp*4 + 0)*32 + lane];
            a1 += red[(warp*4 + 1)*32 + lane];
            a2 += red[(warp*4 + 2)*32 + lane];
            a3 += red[(warp*4 + 3)*32 + lane];
            float zi = a0 + xi, zf = a1 + xf, zg = a2 + xg, zo = a3 + xo;
            float cn = sigm(zf)*c + sigm(zi)*tanhf(zg);
            float hn = sigm(zo)*tanhf(cn);
            c = cn;
            __stcg(&g_cur[d][ph^1][u*32 + lane], hn);                    // state
            __stcg(&g_hT[d][((size_t)txw*H_ + u)*32 + lane], hn);        // archive
        }

        // grid barrier (sense via monotonically increasing generation)
        __syncthreads();
        if (tid == 0) {
            __threadfence();
            int a = atomicAdd(&g_cnt, 1);
            if (a == NBLK - 1) {
                atomicExch(&g_cnt, 0);
                __threadfence();
                atomicExch(&g_gen, t + 1);
            } else {
                while (*(volatile int*)&g_gen <= t) { }
            }
            __threadfence();
        }
        __syncthreads();
    }
}

// ---------------- 4) output projection feats[b,t,k] -------------------------
__global__ void feats_kernel(const float* __restrict__ Wout,
                             const float* __restrict__ bout)
{
    __shared__ float Ws[32][65];
    __shared__ float Rs[32][65];

    const int tid = threadIdx.x;
    const int tok = tid >> 5;
    const int k   = tid & 31;

    const int m = blockIdx.x * 32 + tok;   // m = b*T + t
    float acc = 0.0f;

    for (int j0 = 0; j0 < 2*H_; j0 += 64) {
        __syncthreads();
        for (int i = tid; i < 32*64; i += 1024) {
            int kk = i >> 6, jj = i & 63;
            Ws[kk][jj] = Wout[kk * (2*H_) + j0 + jj];
        }
        for (int i = tid; i < 32*64; i += 1024) {
            int tk = i >> 6, jj = i & 63;
            int mm = blockIdx.x * 32 + tk;
            int bb = mm >> 8, tt = mm & 255;
            int j = j0 + jj;
            // h archive layout: [d][(t*512+u)*32+b]
            Rs[tk][jj] = g_hT[j >> 9][((size_t)tt*H_ + (j & 511))*32 + bb];
        }
        __syncthreads();
        #pragma unroll
        for (int jj = 0; jj < 64; jj++)
            acc += Ws[k][jj] * Rs[tok][jj];
    }
    g_feats[(size_t)m * K_ + k] = acc + bout[k];
}

// ---------------- 5) Viterbi decode + backtrack ------------------------------
__global__ void viterbi_kernel(const float* __restrict__ trans,
                               float* __restrict__ out, int path_base)
{
    __shared__ float tr[32][33];
    const int tid = threadIdx.x;
    tr[tid >> 5][tid & 31] = trans[tid];
    __syncthreads();

    const int b    = tid >> 5;   // batch (warp)
    const int lane = tid & 31;   // next-tag

    float v = (lane == 30) ? 0.0f : NEG_;   // START = 30

    for (int t = 0; t < T_; t++) {
        float ft = g_feats[(size_t)(b * T_ + t) * K_ + lane];
        float best = -3.4e38f;
        int   bp   = 0;
        float vcur = v;
        #pragma unroll
        for (int p = 0; p < 32; p++) {
            float vp = __shfl_sync(0xffffffffu, vcur, p);
            float s = vp + tr[lane][p];
            if (s > best) { best = s; bp = p; }   // first-index tie-break
        }
        v = best + ft;
        g_bp[(size_t)(t * 32 + b) * 32 + lane] = (unsigned char)bp;
    }

    float term = v + tr[31][lane];           // STOP = 31

    float bv = term; int bi = lane;
    #pragma unroll
    for (int off = 16; off > 0; off >>= 1) {
        float ov = __shfl_down_sync(0xffffffffu, bv, off);
        int   oi = __shfl_down_sync(0xffffffffu, bi, off);
        if (ov > bv || (ov == bv && oi < bi)) { bv = ov; bi = oi; }
    }
    bi = __shfl_sync(0xffffffffu, bi, 0);
    bv = __shfl_sync(0xffffffffu, bv, 0);

    if (lane == 0) {
        if (path_base > 0) out[b] = bv;     // path_score
        int tag = bi;
        for (int t = T_ - 1; t >= 0; t--) {
            out[path_base + b * T_ + t] = (float)tag;
            tag = g_bp[(size_t)(t * 32 + b) * 32 + tag];
        }
    }
}

// ---------------- launch -----------------------------------------------------
extern "C" void kernel_launch(void* const* d_in, const int* in_sizes, int n_in,
                              void* d_out, int out_size)
{
    // unit: elements vs bytes (emb unique: 12,800,000 elems / 51,200,000 B)
    int unit = 0;
    for (int i = 0; i < n_in; i++) {
        if (in_sizes[i] == 12800000) { unit = 1; break; }
        if (in_sizes[i] == 51200000) { unit = 4; break; }
    }

    int i_sent = -1, i_emb = -1, i_bout = -1, i_tr = -1, sent64 = 0;
    int gih[2], nih = 0, ghh[2], nhh = 0, g2i[2], n2 = 0, g3i[3], n3 = 0;
    if (unit) {
        for (int i = 0; i < n_in; i++) {
            const int s = in_sizes[i] / unit;
            if      (s == 8192)     { if (i_sent < 0) { i_sent = i; sent64 = 0; } }
            else if (s == 16384)    { if (i_sent < 0) { i_sent = i; sent64 = 1; } }
            else if (s == 12800000) { if (i_emb  < 0) i_emb  = i; }
            else if (s == 32)       { if (i_bout < 0) i_bout = i; }
            else if (s == 1024)     { if (i_tr   < 0) i_tr   = i; }
            else if (s == 524288)   { if (nih < 2) gih[nih++] = i; }
            else if (s == 1048576)  { if (nhh < 2) ghh[nhh++] = i; }
            else if (s == 2048)     { if (n2  < 2) g2i[n2++]  = i; }
            else if (s == 32768)    { if (n3  < 3) g3i[n3++]  = i; }
        }
    }
    const int out_elems = (unit == 4) ? out_size / 4 : out_size;

    if (!unit || i_sent < 0 || i_emb < 0 || i_bout < 0 || i_tr < 0 ||
        nih != 2 || nhh != 2 || n2 != 2 || n3 != 3) {
        int n = out_size > 0 ? out_size : 1;
        fill_out<<<(n + 255) / 256, 256>>>((float*)d_out, n, 1.0e6f);
        return;
    }

    int I_Wihf, I_Whhf, I_Wihb, I_Whhb, I_bf, I_bb, I_Wout, I_h0, I_c0;
    if (i_sent < i_emb) {   // dict order
        I_Wihf = gih[0]; I_Wihb = gih[1];
        I_Whhf = ghh[0]; I_Whhb = ghh[1];
        I_bf   = g2i[0]; I_bb   = g2i[1];
        I_Wout = g3i[0]; I_h0   = g3i[1]; I_c0 = g3i[2];
    } else {                // name-sorted order
        I_Whhb = ghh[0]; I_Whhf = ghh[1];
        I_Wihb = gih[0]; I_Wihf = gih[1];
        I_bb   = g2i[0]; I_bf   = g2i[1];
        I_Wout = g3i[0]; I_c0   = g3i[1]; I_h0 = g3i[2];
    }

    const void*  sentence = d_in[i_sent];
    const float* emb      = (const float*)d_in[i_emb];
    const float* W_ih_f   = (const float*)d_in[I_Wihf];
    const float* W_hh_f   = (const float*)d_in[I_Whhf];
    const float* b_f      = (const float*)d_in[I_bf];
    const float* W_ih_b   = (const float*)d_in[I_Wihb];
    const float* W_hh_b   = (const float*)d_in[I_Whhb];
    const float* b_b      = (const float*)d_in[I_bb];
    const float* W_out    = (const float*)d_in[I_Wout];
    const float* b_out    = (const float*)d_in[i_bout];
    const float* trans    = (const float*)d_in[i_tr];
    const float* h0       = (const float*)d_in[I_h0];
    const float* c0       = (const float*)d_in[I_c0];
    float* out = (float*)d_out;

    const int path_base = (out_elems >= B_ + B_*T_) ? B_ : 0;

    const int SMEM_P = (32*512 + 512*33 + 8*4*32) * 4;   // 137216 B
    cudaFuncSetAttribute(lstm_persist,
                         cudaFuncAttributeMaxDynamicSharedMemorySize, SMEM_P);

    gemm_xw<<<dim3(32, 64), 256>>>(sentence, sent64, emb, W_ih_f, W_ih_b, b_f, b_b);
    xw_transpose<<<dim3(64, 256, 2), 256>>>();
    init_state<<<64, 512>>>(h0);
    lstm_persist<<<NBLK, 512, SMEM_P>>>(W_hh_f, W_hh_b, c0);
    feats_kernel<<<256, 1024>>>(W_out, b_out);
    viterbi_kernel<<<1, 1024>>>(trans, out, path_base);
}

// round 8
// speedup vs baseline: 2.5232x; 1.1763x over previous
#include <cuda_runtime.h>
#include <math.h>
#include <stdint.h>

#define B_  32
#define T_  256
#define E_  256            // V,E,H,K = 50000,256,512,32
#define H_  512
#define K_  32
#define V_  50000
#define G4  2048           // 4*H
#define M_  (T_*B_)        // 8192 tokens
#define NEG_ -10000.0f
#define PITCH 516          // hsm row pitch (floats): /4 == 129 ≡ 1 mod 8

// ---------------- scratch (static device globals; no allocation) -------------
__device__ float g_xwT[2][M_*G4];         // [d][(t*2048+n)*32+b]
__device__ float g_hT [2][M_*H_];         // [d][(t*512+u)*32+b]
__device__ float g_cur[2][2][H_*B_];      // [d][phase][u*32+b]
__device__ float g_feats[B_*T_*K_];       // [m][k], m=b*T+t
__device__ unsigned char g_bp[T_*B_*K_];
__device__ int g_cnt2[2];                 // per-direction grid barrier
__device__ int g_gen2[2];

__device__ __forceinline__ float sigm(float x){ return 1.0f/(1.0f+expf(-x)); }

__device__ __forceinline__ void fma2(unsigned long long &acc,
                                     unsigned long long a, unsigned long long b){
    asm("fma.rn.f32x2 %0, %1, %2, %0;" : "+l"(acc) : "l"(a), "l"(b));
}
__device__ __forceinline__ unsigned long long dup2(float a){
    unsigned long long d;
    asm("mov.b64 %0, {%1, %1};" : "=l"(d) : "f"(a));
    return d;
}
__device__ __forceinline__ float collapse2(unsigned long long v){
    float lo, hi;
    asm("mov.b64 {%0, %1}, %2;" : "=f"(lo), "=f"(hi) : "l"(v));
    return lo + hi;
}

__global__ void fill_out(float* out, int n, float val)
{
    int i = blockIdx.x * blockDim.x + threadIdx.x;
    if (i < n) out[i] = val;
}

// ---------------- 1) embedding-gather + input GEMM + fused transpose --------
// writes g_xwT[d][(t*2048+n)*32+b] directly.
__global__ void gemm_xw(const void* __restrict__ sentence, int sent64,
                        const float* __restrict__ emb,
                        const float* __restrict__ Wf,
                        const float* __restrict__ Wb,
                        const float* __restrict__ bf,
                        const float* __restrict__ bb)
{
    extern __shared__ float smg[];
    float* As   = smg;            // [8][128]
    float* Bs   = smg + 1024;     // [8][128]
    float* tile = smg + 2048;     // [128][129]

    const int bx = blockIdx.x;    // 0..31 (N tiles)
    const int by = blockIdx.y;    // 0..63 (M tiles)
    const int tid = threadIdx.x;
    const int tx = tid & 15;
    const int ty = tid >> 4;

    const int arow  = tid >> 1;
    const int acol4 = (tid & 1) * 4;
    const int r  = by * 128 + arow;
    const int tt = r >> 5;
    const int bb_ = r & 31;
    long long w64 = sent64 ? ((const long long*)sentence)[bb_ * T_ + tt]
                           : (long long)((const int*)sentence)[bb_ * T_ + tt];
    unsigned int word = (unsigned int)w64;
    if (word >= V_) word = 0;
    const float* aptr = emb + (size_t)word * E_;

    const int brow  = tid >> 1;
    const int bcol4 = (tid & 1) * 4;
    const int n = bx * 128 + brow;
    const float* wptr = (n < G4) ? (Wf + (size_t)n * E_)
                                 : (Wb + (size_t)(n - G4) * E_);

    unsigned long long acc2[8][4];
    #pragma unroll
    for (int i = 0; i < 8; i++)
        #pragma unroll
        for (int j = 0; j < 4; j++) acc2[i][j] = 0ull;

    for (int k0 = 0; k0 < E_; k0 += 8) {
        float4 a4 = *(const float4*)(aptr + k0 + acol4);
        float4 b4 = *(const float4*)(wptr + k0 + bcol4);
        __syncthreads();
        As[(acol4+0)*128 + arow] = a4.x; As[(acol4+1)*128 + arow] = a4.y;
        As[(acol4+2)*128 + arow] = a4.z; As[(acol4+3)*128 + arow] = a4.w;
        Bs[(bcol4+0)*128 + brow] = b4.x; Bs[(bcol4+1)*128 + brow] = b4.y;
        Bs[(bcol4+2)*128 + brow] = b4.z; Bs[(bcol4+3)*128 + brow] = b4.w;
        __syncthreads();
        #pragma unroll
        for (int k = 0; k < 8; k++) {
            float4 a0 = *(const float4*)&As[k*128 + ty*8];
            float4 a1 = *(const float4*)&As[k*128 + ty*8 + 4];
            ulonglong2 bq0 = *(const ulonglong2*)&Bs[k*128 + tx*8];
            ulonglong2 bq1 = *(const ulonglong2*)&Bs[k*128 + tx*8 + 4];
            float av[8] = {a0.x,a0.y,a0.z,a0.w,a1.x,a1.y,a1.z,a1.w};
            #pragma unroll
            for (int i = 0; i < 8; i++) {
                unsigned long long ap = dup2(av[i]);
                fma2(acc2[i][0], ap, bq0.x);
                fma2(acc2[i][1], ap, bq0.y);
                fma2(acc2[i][2], ap, bq1.x);
                fma2(acc2[i][3], ap, bq1.y);
            }
        }
    }

    // stage results into smem tile (m_local x n_local)
    __syncthreads();
    #pragma unroll
    for (int i = 0; i < 8; i++) {
        const int ml = ty*8 + i;
        #pragma unroll
        for (int jp = 0; jp < 4; jp++) {
            float lo, hi;
            asm("mov.b64 {%0, %1}, %2;" : "=f"(lo), "=f"(hi) : "l"(acc2[i][jp]));
            tile[ml*129 + tx*8 + jp*2    ] = lo;
            tile[ml*129 + tx*8 + jp*2 + 1] = hi;
        }
    }
    __syncthreads();

    // coalesced transposed write-out: xwT[(t*2048+n)*32+b]
    const int d = bx >> 4;
    const int jjbase = bx * 128 - d * G4;
    const float* bias = d ? bb : bf;
    float* outp = g_xwT[d];
    const int wid  = tid >> 5;
    const int lane = tid & 31;
    #pragma unroll 8
    for (int it = 0; it < 64; it++) {
        int group = wid*64 + it;          // 0..511
        int nl = group >> 2;              // n_local
        int tg = group & 3;               // t sub-group
        float v = tile[(tg*32 + lane)*129 + nl] + bias[jjbase + nl];
        outp[((size_t)(by*4 + tg)*G4 + jjbase + nl)*32 + lane] = v;
    }
}

// ---------------- 2) init: h0 -> cur[phase 0], reset barriers ----------------
__global__ void init_state(const float* __restrict__ h0)
{
    int i = blockIdx.x * blockDim.x + threadIdx.x;
    if (i < 2) { g_cnt2[i] = 0; g_gen2[i] = 0; }
    if (i < 2*B_*H_) {
        int d = i / (B_*H_);
        int r = i % (B_*H_);
        int b = r / H_, u = r % H_;
        g_cur[d][0][u*32 + b] = h0[i];
    }
}

// ---------------- 3) persistent bidirectional LSTM recurrence ---------------
// 128 blocks x 512 threads (16 warps). Block = 8 units x 4 gates, one dir.
// warp = (unit-pair p=warp&3, k-quarter kq=warp>>2); lane = batch.
__global__ void __launch_bounds__(512, 1)
lstm_persist(const float* __restrict__ Whhf,
             const float* __restrict__ Whhb,
             const float* __restrict__ c0)
{
    extern __shared__ float sm[];
    float* Wsm = sm;                  // [32][512] rows: g*8 + unit_local
    float* hsm = Wsm + 32*512;        // [32][PITCH] row=batch, col=k (swizzled)
    float* red = hsm + 32*PITCH;      // [12][8][32]

    const int tid  = threadIdx.x;
    const int bid  = blockIdx.x;
    const int warp = tid >> 5;
    const int lane = tid & 31;
    const int d    = bid >> 6;
    const int ub   = (bid & 63) * 8;
    const float* W = d ? Whhb : Whhf;

    for (int i = tid; i < 32*512; i += 512) {
        int rr = i >> 9, k = i & 511;
        int gg = rr >> 3, ii = rr & 7;
        Wsm[rr*512 + k] = W[(size_t)(gg*H_ + ub + ii)*H_ + k];
    }

    const int p  = warp & 3;          // unit pair: units 2p, 2p+1
    const int kq = warp >> 2;         // k quarter
    const int k0 = kq * 128;
    const int u0 = ub + 2*p;
    const int kx = 8 * (lane & 3);    // smem swizzle

    float c[2] = {0.f, 0.f};
    if (kq == 0) {
        c[0] = c0[d*(B_*H_) + lane*H_ + u0    ];
        c[1] = c0[d*(B_*H_) + lane*H_ + u0 + 1];
    }
    const float* xwT = g_xwT[d];

    for (int t = 0; t < T_; t++) {
        const int ph  = t & 1;
        const int txw = d ? (T_ - 1 - t) : t;

        // stage h_prev into hsm (swizzled, conflict-free STS.128)
        {
            const float* cp = g_cur[d][ph];
            #pragma unroll
            for (int it = 0; it < 8; it++) {
                int q  = tid + it*512;          // 0..4095 quads
                int b  = q & 31;
                int uu = (q >> 5) << 2;
                float4 v;
                v.x = __ldcg(cp + (uu+0)*32 + b);
                v.y = __ldcg(cp + (uu+1)*32 + b);
                v.z = __ldcg(cp + (uu+2)*32 + b);
                v.w = __ldcg(cp + (uu+3)*32 + b);
                *(float4*)&hsm[b*PITCH + (uu ^ (8*(b&3)))] = v;
            }
        }

        // xw prefetch (finalizing warps only)
        float xv[8];
        if (kq == 0) {
            const float* bp = xwT + (size_t)txw * G4 * 32 + lane;
            #pragma unroll
            for (int g = 0; g < 4; g++) {
                xv[g*2+0] = __ldcg(bp + (g*H_ + u0    )*32);
                xv[g*2+1] = __ldcg(bp + (g*H_ + u0 + 1)*32);
            }
        }
        __syncthreads();

        // 8 rows (4 gates x 2 units) over this warp's k-quarter, FFMA2-packed
        unsigned long long acc[8];
        #pragma unroll
        for (int rr = 0; rr < 8; rr++) acc[rr] = 0ull;
        const float* hrow = hsm + lane*PITCH;
        #pragma unroll 8
        for (int q = 0; q < 32; q++) {
            const int k = k0 + q*4;
            ulonglong2 hv = *(const ulonglong2*)&hrow[k ^ kx];
            #pragma unroll
            for (int g = 0; g < 4; g++) {
                ulonglong2 w0 = *(const ulonglong2*)&Wsm[(g*8 + 2*p    )*512 + k];
                ulonglong2 w1 = *(const ulonglong2*)&Wsm[(g*8 + 2*p + 1)*512 + k];
                fma2(acc[g*2+0], w0.x, hv.x); fma2(acc[g*2+0], w0.y, hv.y);
                fma2(acc[g*2+1], w1.x, hv.x); fma2(acc[g*2+1], w1.y, hv.y);
            }
        }
        float av[8];
        #pragma unroll
        for (int rr = 0; rr < 8; rr++) av[rr] = collapse2(acc[rr]);

        if (kq > 0) {
            #pragma unroll
            for (int rr = 0; rr < 8; rr++)
                red[(((kq-1)*4 + p)*8 + rr)*32 + lane] = av[rr];
        }
        __syncthreads();

        if (kq == 0) {
            #pragma unroll
            for (int rr = 0; rr < 8; rr++)
                av[rr] += red[((0*4 + p)*8 + rr)*32 + lane]
                        + red[((1*4 + p)*8 + rr)*32 + lane]
                        + red[((2*4 + p)*8 + rr)*32 + lane];
            #pragma unroll
            for (int e = 0; e < 2; e++) {
                float zi = av[0*2+e] + xv[0*2+e];
                float zf = av[1*2+e] + xv[1*2+e];
                float zg = av[2*2+e] + xv[2*2+e];
                float zo = av[3*2+e] + xv[3*2+e];
                float cn = sigm(zf)*c[e] + sigm(zi)*tanhf(zg);
                float hn = sigm(zo)*tanhf(cn);
                c[e] = cn;
                const int u = u0 + e;
                __stcg(&g_cur[d][ph^1][u*32 + lane], hn);
                __stcg(&g_hT[d][((size_t)txw*H_ + u)*32 + lane], hn);
            }
        }

        __syncthreads();
        if (t < T_ - 1) {
            if (tid == 0) {
                __threadfence();
                int a = atomicAdd(&g_cnt2[d], 1);
                if (a == 63) {
                    atomicExch(&g_cnt2[d], 0);
                    __threadfence();
                    atomicExch(&g_gen2[d], t + 1);
                } else {
                    while (*(volatile int*)&g_gen2[d] <= t) { }
                }
                __threadfence();
            }
            __syncthreads();
        }
    }
}

// ---------------- 4) output projection feats[b,t,k] -------------------------
__global__ void feats_kernel(const float* __restrict__ Wout,
                             const float* __restrict__ bout)
{
    __shared__ float Ws[32][65];
    __shared__ float Rs[32][65];

    const int tid = threadIdx.x;
    const int tok = tid >> 5;
    const int k   = tid & 31;

    const int m = blockIdx.x * 32 + tok;   // m = b*T + t
    float acc = 0.0f;

    for (int j0 = 0; j0 < 2*H_; j0 += 64) {
        __syncthreads();
        for (int i = tid; i < 32*64; i += 1024) {
            int kk = i >> 6, jj = i & 63;
            Ws[kk][jj] = Wout[kk * (2*H_) + j0 + jj];
        }
        for (int i = tid; i < 32*64; i += 1024) {
            int tk = i >> 6, jj = i & 63;
            int mm = blockIdx.x * 32 + tk;
            int bb = mm >> 8, tt = mm & 255;
            int j = j0 + jj;
            Rs[tk][jj] = g_hT[j >> 9][((size_t)tt*H_ + (j & 511))*32 + bb];
        }
        __syncthreads();
        #pragma unroll
        for (int jj = 0; jj < 64; jj++)
            acc += Ws[k][jj] * Rs[tok][jj];
    }
    g_feats[(size_t)m * K_ + k] = acc + bout[k];
}

// ---------------- 5) Viterbi decode + backtrack ------------------------------
__global__ void viterbi_kernel(const float* __restrict__ trans,
                               float* __restrict__ out, int path_base)
{
    __shared__ float tr[32][33];
    const int tid = threadIdx.x;
    tr[tid >> 5][tid & 31] = trans[tid];
    __syncthreads();

    const int b    = tid >> 5;
    const int lane = tid & 31;

    float v = (lane == 30) ? 0.0f : NEG_;   // START = 30

    for (int t = 0; t < T_; t++) {
        float ft = g_feats[(size_t)(b * T_ + t) * K_ + lane];
        float best = -3.4e38f;
        int   bp   = 0;
        float vcur = v;
        #pragma unroll
        for (int p = 0; p < 32; p++) {
            float vp = __shfl_sync(0xffffffffu, vcur, p);
            float s = vp + tr[lane][p];
            if (s > best) { best = s; bp = p; }
        }
        v = best + ft;
        g_bp[(size_t)(t * 32 + b) * 32 + lane] = (unsigned char)bp;
    }

    float term = v + tr[31][lane];           // STOP = 31

    float bv = term; int bi = lane;
    #pragma unroll
    for (int off = 16; off > 0; off >>= 1) {
        float ov = __shfl_down_sync(0xffffffffu, bv, off);
        int   oi = __shfl_down_sync(0xffffffffu, bi, off);
        if (ov > bv || (ov == bv && oi < bi)) { bv = ov; bi = oi; }
    }
    bi = __shfl_sync(0xffffffffu, bi, 0);
    bv = __shfl_sync(0xffffffffu, bv, 0);

    if (lane == 0) {
        if (path_base > 0) out[b] = bv;
        int tag = bi;
        for (int t = T_ - 1; t >= 0; t--) {
            out[path_base + b * T_ + t] = (float)tag;
            tag = g_bp[(size_t)(t * 32 + b) * 32 + tag];
        }
    }
}

// ---------------- launch -----------------------------------------------------
extern "C" void kernel_launch(void* const* d_in, const int* in_sizes, int n_in,
                              void* d_out, int out_size)
{
    int unit = 0;
    for (int i = 0; i < n_in; i++) {
        if (in_sizes[i] == 12800000) { unit = 1; break; }
        if (in_sizes[i] == 51200000) { unit = 4; break; }
    }

    int i_sent = -1, i_emb = -1, i_bout = -1, i_tr = -1, sent64 = 0;
    int gih[2], nih = 0, ghh[2], nhh = 0, g2i[2], n2 = 0, g3i[3], n3 = 0;
    if (unit) {
        for (int i = 0; i < n_in; i++) {
            const int s = in_sizes[i] / unit;
            if      (s == 8192)     { if (i_sent < 0) { i_sent = i; sent64 = 0; } }
            else if (s == 16384)    { if (i_sent < 0) { i_sent = i; sent64 = 1; } }
            else if (s == 12800000) { if (i_emb  < 0) i_emb  = i; }
            else if (s == 32)       { if (i_bout < 0) i_bout = i; }
            else if (s == 1024)     { if (i_tr   < 0) i_tr   = i; }
            else if (s == 524288)   { if (nih < 2) gih[nih++] = i; }
            else if (s == 1048576)  { if (nhh < 2) ghh[nhh++] = i; }
            else if (s == 2048)     { if (n2  < 2) g2i[n2++]  = i; }
            else if (s == 32768)    { if (n3  < 3) g3i[n3++]  = i; }
        }
    }
    const int out_elems = (unit == 4) ? out_size / 4 : out_size;

    if (!unit || i_sent < 0 || i_emb < 0 || i_bout < 0 || i_tr < 0 ||
        nih != 2 || nhh != 2 || n2 != 2 || n3 != 3) {
        int n = out_size > 0 ? out_size : 1;
        fill_out<<<(n + 255) / 256, 256>>>((float*)d_out, n, 1.0e6f);
        return;
    }

    int I_Wihf, I_Whhf, I_Wihb, I_Whhb, I_bf, I_bb, I_Wout, I_h0, I_c0;
    if (i_sent < i_emb) {   // dict order
        I_Wihf = gih[0]; I_Wihb = gih[1];
        I_Whhf = ghh[0]; I_Whhb = ghh[1];
        I_bf   = g2i[0]; I_bb   = g2i[1];
        I_Wout = g3i[0]; I_h0   = g3i[1]; I_c0 = g3i[2];
    } else {                // name-sorted order
        I_Whhb = ghh[0]; I_Whhf = ghh[1];
        I_Wihb = gih[0]; I_Wihf = gih[1];
        I_bb   = g2i[0]; I_bf   = g2i[1];
        I_Wout = g3i[0]; I_c0   = g3i[1]; I_h0 = g3i[2];
    }

    const void*  sentence = d_in[i_sent];
    const float* emb      = (const float*)d_in[i_emb];
    const float* W_ih_f   = (const float*)d_in[I_Wihf];
    const float* W_hh_f   = (const float*)d_in[I_Whhf];
    const float* b_f      = (const float*)d_in[I_bf];
    const float* W_ih_b   = (const float*)d_in[I_Wihb];
    const float* W_hh_b   = (const float*)d_in[I_Whhb];
    const float* b_b      = (const float*)d_in[I_bb];
    const float* W_out    = (const float*)d_in[I_Wout];
    const float* b_out    = (const float*)d_in[i_bout];
    const float* trans    = (const float*)d_in[i_tr];
    const float* h0       = (const float*)d_in[I_h0];
    const float* c0       = (const float*)d_in[I_c0];
    float* out = (float*)d_out;

    const int path_base = (out_elems >= B_ + B_*T_) ? B_ : 0;

    const int SMEM_G = (2048 + 128*129) * 4;                 // 74240 B
    const int SMEM_P = (32*512 + 32*PITCH + 12*8*32) * 4;    // 143872 B
    cudaFuncSetAttribute(gemm_xw,
                         cudaFuncAttributeMaxDynamicSharedMemorySize, SMEM_G);
    cudaFuncSetAttribute(lstm_persist,
                         cudaFuncAttributeMaxDynamicSharedMemorySize, SMEM_P);

    gemm_xw<<<dim3(32, 64), 256, SMEM_G>>>(sentence, sent64, emb,
                                           W_ih_f, W_ih_b, b_f, b_b);
    init_state<<<64, 512>>>(h0);
    lstm_persist<<<128, 512, SMEM_P>>>(W_hh_f, W_hh_b, c0);
    feats_kernel<<<256, 1024>>>(W_out, b_out);
    viterbi_kernel<<<1, 1024>>>(trans, out, path_base);
}